// round 14
// baseline (speedup 1.0000x reference)
#include <cuda_runtime.h>
#include <math.h>
#include <stdint.h>

#define SCALE 16
#define R_MAX 4
#define HL 32
#define WL 32
#define HH 512
#define WH 512
#define C_FEAT 128
#define HW (HH * WH)

// prep scratch
__device__ float g_guide_lr[3 * HL * WL];
__device__ float g_feat_t[HL * WL * C_FEAT];   // [spatial][channel]

// ---------------- dynamic smem layout (bytes) ----------------
// F packed as uint4 {hi@kpair q, hi@kpair q+4, lo@q, lo@q+4} indexed
// [ks*4+lr][channel], stride 130 uint4 (130 mod 8 = 2): conflict-free
// LDS.128 fragment loads and STS.128 builds.
#define CSTR4 130
#define OFF_SCAL   0            // floats: ct, st, isx, isy, isr, Rsq
#define OFF_NACT   32
#define OFF_SI     64           // int[64]
#define OFF_DXF    320          // float[64]
#define OFF_DYF    576          // float[64]
#define OFF_P0     832          // float4[64]
#define OFF_P1     1856         // float2[64]
#define OFF_F4     2432         // uint4[16][CSTR4]
#define SMEM_BYTES (OFF_F4 + 16 * CSTR4 * 16)   // 35712 B

// pack two floats to bf16x2 (lo 16 bits = w0)
static __device__ __forceinline__ uint32_t pack_bf16x2(float w0, float w1) {
    uint32_t r;
    asm("cvt.rn.bf16x2.f32 %0, %1, %2;" : "=r"(r) : "f"(w1), "f"(w0));
    return r;
}

#define MMA_BF16(d, a0, a1, a2, a3, b0, b1) \
    asm volatile("mma.sync.aligned.m16n8k16.row.col.f32.bf16.bf16.f32 " \
        "{%0,%1,%2,%3}, {%4,%5,%6,%7}, {%8,%9}, {%0,%1,%2,%3};" \
        : "+f"((d)[0]), "+f"((d)[1]), "+f"((d)[2]), "+f"((d)[3]) \
        : "r"(a0), "r"(a1), "r"(a2), "r"(a3), "r"(b0), "r"(b1))

// ---------------------------------------------------------------------------
// Prep: transpose feat to channel-minor; bilinear-downsample guide (separable,
// rows then columns, matching the reference).
// ---------------------------------------------------------------------------
__global__ void jbu_prep_kernel(const float* __restrict__ feat,
                                const float* __restrict__ guide) {
    int idx = blockIdx.x * blockDim.x + threadIdx.x;

    if (idx < HL * WL * C_FEAT) {
        int c = idx & (C_FEAT - 1);
        int s = idx >> 7;
        g_feat_t[idx] = feat[c * (HL * WL) + s];
    }
    if (idx < 3 * HL * WL) {
        int c = idx >> 10;
        int rem = idx & 1023;
        int i = rem >> 5;
        int j = rem & 31;

        float srcy = fmaxf((i + 0.5f) * ((float)HH / HL) - 0.5f, 0.0f);
        int r0 = (int)floorf(srcy);
        float tr = srcy - (float)r0;
        int r0c = min(max(r0, 0), HH - 1);
        int r1c = min(max(r0 + 1, 0), HH - 1);

        float srcx = fmaxf((j + 0.5f) * ((float)WH / WL) - 0.5f, 0.0f);
        int c0 = (int)floorf(srcx);
        float tc = srcx - (float)c0;
        int c0c = min(max(c0, 0), WH - 1);
        int c1c = min(max(c0 + 1, 0), WH - 1);

        const float* g = guide + c * HW;
        float v0 = g[r0c * WH + c0c] * (1.0f - tr) + g[r1c * WH + c0c] * tr;
        float v1 = g[r0c * WH + c1c] * (1.0f - tr) + g[r1c * WH + c1c] * tr;
        g_guide_lr[idx] = v0 * (1.0f - tc) + v1 * tc;
    }
}

// ---------------------------------------------------------------------------
// Main: one block per HALF LR cell (8 HR rows x 16 cols x 128 ch).
// 128 threads, 4 warps; warp w owns HR rows 2w and 2w+1 (2 m-tiles) so every
// B fragment (one LDS.128) feeds 6 MMAs. W fragments for all k-steps and both
// m-tiles computed in registers first; channels streamed with transient accs.
// Guide LDGs hoisted to kernel entry; regs capped for 6 blocks/SM.
// ---------------------------------------------------------------------------
__global__ __launch_bounds__(128, 6)
void jbu_main_kernel(const float* __restrict__ guide,
                     const float* __restrict__ sx_raw,
                     const float* __restrict__ sy_raw,
                     const float* __restrict__ th_raw,
                     const float* __restrict__ sr_raw,
                     float* __restrict__ out) {
    extern __shared__ __align__(16) char smem[];

    float*    s_scal = (float*)(smem + OFF_SCAL);
    int*      s_nactp = (int*)(smem + OFF_NACT);
    int*      s_si   = (int*)(smem + OFF_SI);
    float*    s_dxf  = (float*)(smem + OFF_DXF);
    float*    s_dyf  = (float*)(smem + OFF_DYF);
    float4*   s_p0   = (float4*)(smem + OFF_P0);
    float2*   s_p1   = (float2*)(smem + OFF_P1);
    uint4*    F4     = (uint4*)(smem + OFF_F4);

    const int uc = blockIdx.y;
    const int vc = blockIdx.x;
    const int zh = blockIdx.z;       // 0/1: which 8-row half of the 16x16 tile
    const int tid = threadIdx.x;
    const int wid = tid >> 5;        // 0..3
    const int lane = tid & 31;
    const int lq = lane >> 2;        // 0..7  (groupID)
    const int lr = lane & 3;         // 0..3  (threadID-in-group)
    const int x0 = vc * SCALE + lq;  // pixel 0: x=lq; pixel 1: x=lq+8

    // ---- hoisted guide loads (latency overlapped with phases 0-1) ----
    float gA[2][3], gB[2][3];
#pragma unroll
    for (int mt = 0; mt < 2; mt++) {
        const int yy = uc * SCALE + zh * 8 + 2 * wid + mt;
        const float* gp = guide + (size_t)yy * WH + x0;
        gA[mt][0] = gp[0];  gA[mt][1] = gp[HW];     gA[mt][2] = gp[2 * HW];
        gB[mt][0] = gp[8];  gB[mt][1] = gp[HW + 8]; gB[mt][2] = gp[2 * HW + 8];
    }

    // ---- phase 0: params + offset compaction (warp 0, ballot-based) ----
    if (wid == 0) {
        if (lane == 0) {
            int cell = uc * WL + vc;
            float sx = fmaxf(expf(sx_raw[cell]), 1e-6f);
            float sy = fmaxf(expf(sy_raw[cell]), 1e-6f);
            float th = 3.14159265358979323846f * tanhf(th_raw[cell]);
            float sr = fmaxf(expf(sr_raw[cell]), 1e-6f);
            float rr = fminf(fmaxf(2.0f * fmaxf(sx, sy), 1.0f), (float)R_MAX);
            s_scal[0] = cosf(th);
            s_scal[1] = sinf(th);
            s_scal[2] = 1.0f / (2.0f * sx * sx + 1e-8f);
            s_scal[3] = 1.0f / (2.0f * sy * sy + 1e-8f);
            s_scal[4] = 1.0f / (2.0f * sr * sr + 1e-8f);
            s_scal[5] = rr * rr;
        }
        __syncwarp();
        const float Rsq = s_scal[5];
        int base = 0;
#pragma unroll
        for (int chnk = 0; chnk < 3; chnk++) {
            int i = chnk * 32 + lane;
            int dy = i / 9 - R_MAX;
            int dx = i - (i / 9) * 9 - R_MAX;
            bool act = (i < 81) && ((float)(dy * dy + dx * dx) <= Rsq);
            unsigned m = __ballot_sync(0xffffffffu, act);
            int pos = base + __popc(m & ((1u << lane) - 1u));
            if (act) {
                int ui = min(max(uc + dy, 0), HL - 1);
                int vi = min(max(vc + dx, 0), WL - 1);
                s_dyf[pos] = (float)(uc - ui);
                s_dxf[pos] = (float)(vc - vi);
                s_si[pos]  = ui * WL + vi;
            }
            base += __popc(m);
        }
        if (lane == 0) *s_nactp = base;
    }
    __syncthreads();

    const int nact = *s_nactp;                 // <= 49
    const int ksteps = (nact + 15) >> 4;       // <= 4
    const float ct  = s_scal[0];
    const float st  = s_scal[1];
    const float isx = s_scal[2];
    const float isy = s_scal[3];
    const float isr = s_scal[4];

    if (tid < nact) {
        int si = s_si[tid];
        float fdx = s_dxf[tid];
        float fdy = s_dyf[tid];
        float gl0 = g_guide_lr[si];
        float gl1 = g_guide_lr[HL * WL + si];
        float gl2 = g_guide_lr[2 * HL * WL + si];
        float A = fdx * ct + fdy * st;
        float B = fdy * ct - fdx * st;
        float D = (gl0 * gl0 + gl1 * gl1 + gl2 * gl2) * isr;
        s_p0[tid] = make_float4(A, B, D, 2.0f * gl0 * isr);
        s_p1[tid] = make_float2(2.0f * gl1 * isr, 2.0f * gl2 * isr);
    }
    __syncthreads();

    // ---- phase 1: build F4 (all 128 threads; consecutive c -> conflict-free) ----
    {
        const int nent = ksteps * 4 * C_FEAT;
        for (int e = tid; e < nent; e += 128) {
            int c = e & 127;
            int q = e >> 7;                // ks*4 + lr_b
            int kp0 = (q >> 2) * 8 + (q & 3);
            int kp1 = kp0 + 4;
            int k00 = 2 * kp0, k01 = k00 + 1;
            int k10 = 2 * kp1, k11 = k10 + 1;
            float f00 = (k00 < nact) ? g_feat_t[s_si[k00] * C_FEAT + c] : 0.0f;
            float f01 = (k01 < nact) ? g_feat_t[s_si[k01] * C_FEAT + c] : 0.0f;
            float f10 = (k10 < nact) ? g_feat_t[s_si[k10] * C_FEAT + c] : 0.0f;
            float f11 = (k11 < nact) ? g_feat_t[s_si[k11] * C_FEAT + c] : 0.0f;
            uint32_t hi0 = pack_bf16x2(f00, f01);
            uint32_t hi1 = pack_bf16x2(f10, f11);
            uint32_t lo0 = pack_bf16x2(f00 - __uint_as_float(hi0 << 16),
                                       f01 - __uint_as_float(hi0 & 0xffff0000u));
            uint32_t lo1 = pack_bf16x2(f10 - __uint_as_float(hi1 << 16),
                                       f11 - __uint_as_float(hi1 & 0xffff0000u));
            F4[q * CSTR4 + c] = make_uint4(hi0, hi1, lo0, lo1);
        }
    }

    // ---- phase 2a: W fragments for all k-steps, BOTH m-tiles, into regs ----
    uint32_t ah[2][4][4], al[2][4][4];
    float inv[2][2];
    const float nisx = -isx, nisy = -isy;
    const float px0 = ((float)lq - 7.5f) * (1.0f / SCALE);
    const float px1 = ((float)(lq + 8) - 7.5f) * (1.0f / SCALE);

#pragma unroll
    for (int mt = 0; mt < 2; mt++) {
        const int tyc = zh * 8 + 2 * wid + mt;
        const float ga0 = gA[mt][0], ga1 = gA[mt][1], ga2 = gA[mt][2];
        const float gb0 = gB[mt][0], gb1 = gB[mt][1], gb2 = gB[mt][2];
        const float py = ((float)tyc - 7.5f) * (1.0f / SCALE);
        const float pa0 = px0 * ct + py * st;
        const float pb0 = py * ct - px0 * st;
        const float pa1 = px1 * ct + py * st;
        const float pb1 = py * ct - px1 * st;
        const float negE0 = -(ga0 * ga0 + ga1 * ga1 + ga2 * ga2) * isr;
        const float negE1 = -(gb0 * gb0 + gb1 * gb1 + gb2 * gb2) * isr;

        float den0 = 0.0f, den1 = 0.0f;
#pragma unroll
        for (int ks = 0; ks < 4; ks++) {
            if (ks >= ksteps) {
#pragma unroll
                for (int j = 0; j < 4; j++) { ah[mt][ks][j] = 0u; al[mt][ks][j] = 0u; }
                continue;
            }
            float w[4][2];
#pragma unroll
            for (int jp = 0; jp < 4; jp++) {
                int k = 2 * (ks * 8 + lr + ((jp >> 1) << 2)) + (jp & 1);
                float v0 = 0.0f, v1 = 0.0f;
                if (k < nact) {
                    float4 q0 = s_p0[k];
                    float2 q1 = s_p1[k];
                    float a0 = pa0 + q0.x, b0 = pb0 + q0.y;
                    float t0 = negE0 - q0.z;
                    t0 = fmaf(ga0, q0.w, t0);
                    t0 = fmaf(ga1, q1.x, t0);
                    t0 = fmaf(ga2, q1.y, t0);
                    t0 = fmaf(a0 * a0, nisx, t0);
                    t0 = fmaf(b0 * b0, nisy, t0);
                    v0 = __expf(t0);
                    float a1 = pa1 + q0.x, b1 = pb1 + q0.y;
                    float t1 = negE1 - q0.z;
                    t1 = fmaf(gb0, q0.w, t1);
                    t1 = fmaf(gb1, q1.x, t1);
                    t1 = fmaf(gb2, q1.y, t1);
                    t1 = fmaf(a1 * a1, nisx, t1);
                    t1 = fmaf(b1 * b1, nisy, t1);
                    v1 = __expf(t1);
                }
                w[jp][0] = v0;
                w[jp][1] = v1;
            }
            den0 += w[0][0] + w[1][0] + w[2][0] + w[3][0];
            den1 += w[0][1] + w[1][1] + w[2][1] + w[3][1];

            uint32_t h0 = pack_bf16x2(w[0][0], w[1][0]);
            uint32_t h1 = pack_bf16x2(w[0][1], w[1][1]);
            uint32_t h2 = pack_bf16x2(w[2][0], w[3][0]);
            uint32_t h3 = pack_bf16x2(w[2][1], w[3][1]);
            ah[mt][ks][0] = h0; ah[mt][ks][1] = h1; ah[mt][ks][2] = h2; ah[mt][ks][3] = h3;
            al[mt][ks][0] = pack_bf16x2(w[0][0] - __uint_as_float(h0 << 16),
                                        w[1][0] - __uint_as_float(h0 & 0xffff0000u));
            al[mt][ks][1] = pack_bf16x2(w[0][1] - __uint_as_float(h1 << 16),
                                        w[1][1] - __uint_as_float(h1 & 0xffff0000u));
            al[mt][ks][2] = pack_bf16x2(w[2][0] - __uint_as_float(h2 << 16),
                                        w[3][0] - __uint_as_float(h2 & 0xffff0000u));
            al[mt][ks][3] = pack_bf16x2(w[2][1] - __uint_as_float(h3 << 16),
                                        w[3][1] - __uint_as_float(h3 & 0xffff0000u));
        }
        den0 += __shfl_xor_sync(0xffffffffu, den0, 1);
        den0 += __shfl_xor_sync(0xffffffffu, den0, 2);
        den1 += __shfl_xor_sync(0xffffffffu, den1, 1);
        den1 += __shfl_xor_sync(0xffffffffu, den1, 2);
        inv[mt][0] = 1.0f / fmaxf(den0, 1e-8f);
        inv[mt][1] = 1.0f / fmaxf(den1, 1e-8f);
    }

    __syncthreads();   // F4 ready

    // ---- phase 2b: stream channels; 1 LDS.128 feeds 6 MMAs ----
    const int ybase = uc * SCALE + zh * 8 + 2 * wid;
    float* ob0 = out + (size_t)ybase * WH + x0;          // mt 0
    float* ob1 = out + (size_t)(ybase + 1) * WH + x0;    // mt 1

#pragma unroll
    for (int ng = 0; ng < 8; ng++) {
#pragma unroll
        for (int h = 0; h < 2; h++) {
            const int cb = (2 * ng + h) * 8 + lq;
            float acc0[4] = {0.f, 0.f, 0.f, 0.f};
            float acc1[4] = {0.f, 0.f, 0.f, 0.f};
#pragma unroll
            for (int ks = 0; ks < 4; ks++) {
                if (ks >= ksteps) break;
                uint4 B = F4[(ks * 4 + lr) * CSTR4 + cb];
                MMA_BF16(acc0, ah[0][ks][0], ah[0][ks][1], ah[0][ks][2], ah[0][ks][3], B.x, B.y);
                MMA_BF16(acc0, al[0][ks][0], al[0][ks][1], al[0][ks][2], al[0][ks][3], B.x, B.y);
                MMA_BF16(acc0, ah[0][ks][0], ah[0][ks][1], ah[0][ks][2], ah[0][ks][3], B.z, B.w);
                MMA_BF16(acc1, ah[1][ks][0], ah[1][ks][1], ah[1][ks][2], ah[1][ks][3], B.x, B.y);
                MMA_BF16(acc1, al[1][ks][0], al[1][ks][1], al[1][ks][2], al[1][ks][3], B.x, B.y);
                MMA_BF16(acc1, ah[1][ks][0], ah[1][ks][1], ah[1][ks][2], ah[1][ks][3], B.z, B.w);
            }
            const int ch = (2 * ng + h) * 8 + lr * 2;
            float* o0 = ob0 + (size_t)ch * HW;
            float* o1 = ob1 + (size_t)ch * HW;
            o0[0]      = acc0[0] * inv[0][0];
            o0[HW]     = acc0[1] * inv[0][0];
            o0[8]      = acc0[2] * inv[0][1];
            o0[HW + 8] = acc0[3] * inv[0][1];
            o1[0]      = acc1[0] * inv[1][0];
            o1[HW]     = acc1[1] * inv[1][0];
            o1[8]      = acc1[2] * inv[1][1];
            o1[HW + 8] = acc1[3] * inv[1][1];
        }
    }
}

extern "C" void kernel_launch(void* const* d_in, const int* in_sizes, int n_in,
                              void* d_out, int out_size) {
    const float* feat  = (const float*)d_in[0];
    const float* guide = (const float*)d_in[1];
    const float* sx    = (const float*)d_in[2];
    const float* sy    = (const float*)d_in[3];
    const float* th    = (const float*)d_in[4];
    const float* sr    = (const float*)d_in[5];
    float* out = (float*)d_out;

    cudaFuncSetAttribute(jbu_main_kernel,
                         cudaFuncAttributeMaxDynamicSharedMemorySize, SMEM_BYTES);

    jbu_prep_kernel<<<512, 256>>>(feat, guide);
    dim3 grid(WL, HL, 2);
    jbu_main_kernel<<<grid, 128, SMEM_BYTES>>>(guide, sx, sy, th, sr, out);
}

// round 15
// speedup vs baseline: 1.4813x; 1.4813x over previous
#include <cuda_runtime.h>
#include <math.h>
#include <stdint.h>

#define SCALE 16
#define R_MAX 4
#define HL 32
#define WL 32
#define HH 512
#define WH 512
#define C_FEAT 128
#define HW (HH * WH)

// prep scratch
__device__ float g_guide_lr[3 * HL * WL];
__device__ float g_feat_t[HL * WL * C_FEAT];   // [spatial][channel]

// ---------------- dynamic smem layout (bytes) ----------------
// F packed as uint4 {hi@kpair q, hi@kpair q+4, lo@q, lo@q+4} indexed
// [ks*4+lr][channel], stride 130 uint4: conflict-free LDS.128/STS.128.
// Q (lw coefficients) [8 rank rows][64 offsets] tf32, stride 72 words:
// fragment loads hit banks (8*lr + lq) -> bijective, conflict-free.
#define CSTR4 130
#define QSTR  72
#define OFF_SCAL   0            // floats: ct, st, isx, isy, isr, Rsq
#define OFF_NACT   32
#define OFF_SI     64           // int[64]
#define OFF_DXF    320          // float[64]
#define OFF_DYF    576          // float[64]
#define OFF_F4     2432         // uint4[16][CSTR4]
#define OFF_QH     (OFF_F4 + 16 * CSTR4 * 16)      // 35712
#define OFF_QL     (OFF_QH + 8 * QSTR * 4)         // +2304
#define SMEM_BYTES (OFF_QL + 8 * QSTR * 4)         // 40320 B

// pack two floats to bf16x2 (lo 16 bits = w0)
static __device__ __forceinline__ uint32_t pack_bf16x2(float w0, float w1) {
    uint32_t r;
    asm("cvt.rn.bf16x2.f32 %0, %1, %2;" : "=r"(r) : "f"(w1), "f"(w0));
    return r;
}

static __device__ __forceinline__ uint32_t f2tf32(float f) {
    uint32_t r;
    asm("cvt.rna.tf32.f32 %0, %1;" : "=r"(r) : "f"(f));
    return r;
}

#define MMA_BF16(d, a0, a1, a2, a3, b0, b1) \
    asm volatile("mma.sync.aligned.m16n8k16.row.col.f32.bf16.bf16.f32 " \
        "{%0,%1,%2,%3}, {%4,%5,%6,%7}, {%8,%9}, {%0,%1,%2,%3};" \
        : "+f"((d)[0]), "+f"((d)[1]), "+f"((d)[2]), "+f"((d)[3]) \
        : "r"(a0), "r"(a1), "r"(a2), "r"(a3), "r"(b0), "r"(b1))

#define MMA_TF32K8(d, a0, a1, a2, a3, b0, b1) \
    asm volatile("mma.sync.aligned.m16n8k8.row.col.f32.tf32.tf32.f32 " \
        "{%0,%1,%2,%3}, {%4,%5,%6,%7}, {%8,%9}, {%0,%1,%2,%3};" \
        : "+f"((d)[0]), "+f"((d)[1]), "+f"((d)[2]), "+f"((d)[3]) \
        : "r"(a0), "r"(a1), "r"(a2), "r"(a3), "r"(b0), "r"(b1))

// ---------------------------------------------------------------------------
// Prep: transpose feat to channel-minor; bilinear-downsample guide (separable,
// rows then columns, matching the reference).
// ---------------------------------------------------------------------------
__global__ void jbu_prep_kernel(const float* __restrict__ feat,
                                const float* __restrict__ guide) {
    int idx = blockIdx.x * blockDim.x + threadIdx.x;

    if (idx < HL * WL * C_FEAT) {
        int c = idx & (C_FEAT - 1);
        int s = idx >> 7;
        g_feat_t[idx] = feat[c * (HL * WL) + s];
    }
    if (idx < 3 * HL * WL) {
        int c = idx >> 10;
        int rem = idx & 1023;
        int i = rem >> 5;
        int j = rem & 31;

        float srcy = fmaxf((i + 0.5f) * ((float)HH / HL) - 0.5f, 0.0f);
        int r0 = (int)floorf(srcy);
        float tr = srcy - (float)r0;
        int r0c = min(max(r0, 0), HH - 1);
        int r1c = min(max(r0 + 1, 0), HH - 1);

        float srcx = fmaxf((j + 0.5f) * ((float)WH / WL) - 0.5f, 0.0f);
        int c0 = (int)floorf(srcx);
        float tc = srcx - (float)c0;
        int c0c = min(max(c0, 0), WH - 1);
        int c1c = min(max(c0 + 1, 0), WH - 1);

        const float* g = guide + c * HW;
        float v0 = g[r0c * WH + c0c] * (1.0f - tr) + g[r1c * WH + c0c] * tr;
        float v1 = g[r0c * WH + c1c] * (1.0f - tr) + g[r1c * WH + c1c] * tr;
        g_guide_lr[idx] = v0 * (1.0f - tc) + v1 * tc;
    }
}

// ---------------------------------------------------------------------------
// Main: one block per HALF LR cell (8 HR rows x 16 cols x 128 ch).
// lw = P(pixel) + v(pixel)·q(offset) computed via split-tf32 m16n8k8 MMA
// (C seeded with P); exp + bf16-pack feed the main m16n8k16 GEMM (hh+lh+hl).
// 128 threads, 4 warps; warp w owns HR rows 2w, 2w+1.
// ---------------------------------------------------------------------------
__global__ __launch_bounds__(128, 5)
void jbu_main_kernel(const float* __restrict__ guide,
                     const float* __restrict__ sx_raw,
                     const float* __restrict__ sy_raw,
                     const float* __restrict__ th_raw,
                     const float* __restrict__ sr_raw,
                     float* __restrict__ out) {
    extern __shared__ __align__(16) char smem[];

    float*    s_scal = (float*)(smem + OFF_SCAL);
    int*      s_nactp = (int*)(smem + OFF_NACT);
    int*      s_si   = (int*)(smem + OFF_SI);
    float*    s_dxf  = (float*)(smem + OFF_DXF);
    float*    s_dyf  = (float*)(smem + OFF_DYF);
    uint4*    F4     = (uint4*)(smem + OFF_F4);
    uint32_t* Qh     = (uint32_t*)(smem + OFF_QH);
    uint32_t* Ql     = (uint32_t*)(smem + OFF_QL);

    const int uc = blockIdx.y;
    const int vc = blockIdx.x;
    const int zh = blockIdx.z;       // 0/1: which 8-row half of the 16x16 tile
    const int tid = threadIdx.x;
    const int wid = tid >> 5;        // 0..3
    const int lane = tid & 31;

    // ---- phase 0: params + offset compaction (warp 0, ballot-based) ----
    if (wid == 0) {
        if (lane == 0) {
            int cell = uc * WL + vc;
            float sx = fmaxf(expf(sx_raw[cell]), 1e-6f);
            float sy = fmaxf(expf(sy_raw[cell]), 1e-6f);
            float th = 3.14159265358979323846f * tanhf(th_raw[cell]);
            float sr = fmaxf(expf(sr_raw[cell]), 1e-6f);
            float rr = fminf(fmaxf(2.0f * fmaxf(sx, sy), 1.0f), (float)R_MAX);
            s_scal[0] = cosf(th);
            s_scal[1] = sinf(th);
            s_scal[2] = 1.0f / (2.0f * sx * sx + 1e-8f);
            s_scal[3] = 1.0f / (2.0f * sy * sy + 1e-8f);
            s_scal[4] = 1.0f / (2.0f * sr * sr + 1e-8f);
            s_scal[5] = rr * rr;
        }
        __syncwarp();
        const float Rsq = s_scal[5];
        int base = 0;
#pragma unroll
        for (int chnk = 0; chnk < 3; chnk++) {
            int i = chnk * 32 + lane;
            int dy = i / 9 - R_MAX;
            int dx = i - (i / 9) * 9 - R_MAX;
            bool act = (i < 81) && ((float)(dy * dy + dx * dx) <= Rsq);
            unsigned m = __ballot_sync(0xffffffffu, act);
            int pos = base + __popc(m & ((1u << lane) - 1u));
            if (act) {
                int ui = min(max(uc + dy, 0), HL - 1);
                int vi = min(max(vc + dx, 0), WL - 1);
                s_dyf[pos] = (float)(uc - ui);
                s_dxf[pos] = (float)(vc - vi);
                s_si[pos]  = ui * WL + vi;
            }
            base += __popc(m);
        }
        if (lane == 0) *s_nactp = base;
    }
    __syncthreads();

    const int nact = *s_nactp;                 // <= 49
    const int ksteps = (nact + 15) >> 4;       // <= 4
    const float ct  = s_scal[0];
    const float st  = s_scal[1];
    const float isx = s_scal[2];
    const float isy = s_scal[3];
    const float isr = s_scal[4];

    // ---- build Q (lw coefficient matrix): threads 0..63, one offset each ----
    if (tid < 64) {
        float q[6];
        if (tid < nact) {
            int si = s_si[tid];
            float fdx = s_dxf[tid];
            float fdy = s_dyf[tid];
            float gl0 = g_guide_lr[si];
            float gl1 = g_guide_lr[HL * WL + si];
            float gl2 = g_guide_lr[2 * HL * WL + si];
            float A = fdx * ct + fdy * st;
            float B = fdy * ct - fdx * st;
            float D = (gl0 * gl0 + gl1 * gl1 + gl2 * gl2) * isr;
            q[0] = -2.0f * A * isx;
            q[1] = -2.0f * B * isy;
            q[2] = 2.0f * gl0 * isr;
            q[3] = 2.0f * gl1 * isr;
            q[4] = 2.0f * gl2 * isr;
            q[5] = -(A * A * isx + B * B * isy + D);
        } else {
            q[0] = q[1] = q[2] = q[3] = q[4] = 0.0f;
            q[5] = -1e30f;   // lw -> -1e30 -> w = 0
        }
#pragma unroll
        for (int r = 0; r < 6; r++) {
            uint32_t h = f2tf32(q[r]);
            Qh[r * QSTR + tid] = h;
            Ql[r * QSTR + tid] = f2tf32(q[r] - __uint_as_float(h));
        }
        Qh[6 * QSTR + tid] = 0u; Qh[7 * QSTR + tid] = 0u;
        Ql[6 * QSTR + tid] = 0u; Ql[7 * QSTR + tid] = 0u;
    }
    __syncthreads();

    // ---- phase 1: build F4 (all 128 threads; consecutive c -> conflict-free) ----
    {
        const int nent = ksteps * 4 * C_FEAT;
        for (int e = tid; e < nent; e += 128) {
            int c = e & 127;
            int q = e >> 7;                // ks*4 + lr_b
            int kp0 = (q >> 2) * 8 + (q & 3);
            int kp1 = kp0 + 4;
            int k00 = 2 * kp0, k01 = k00 + 1;
            int k10 = 2 * kp1, k11 = k10 + 1;
            float f00 = (k00 < nact) ? g_feat_t[s_si[k00] * C_FEAT + c] : 0.0f;
            float f01 = (k01 < nact) ? g_feat_t[s_si[k01] * C_FEAT + c] : 0.0f;
            float f10 = (k10 < nact) ? g_feat_t[s_si[k10] * C_FEAT + c] : 0.0f;
            float f11 = (k11 < nact) ? g_feat_t[s_si[k11] * C_FEAT + c] : 0.0f;
            uint32_t hi0 = pack_bf16x2(f00, f01);
            uint32_t hi1 = pack_bf16x2(f10, f11);
            uint32_t lo0 = pack_bf16x2(f00 - __uint_as_float(hi0 << 16),
                                       f01 - __uint_as_float(hi0 & 0xffff0000u));
            uint32_t lo1 = pack_bf16x2(f10 - __uint_as_float(hi1 << 16),
                                       f11 - __uint_as_float(hi1 & 0xffff0000u));
            F4[q * CSTR4 + c] = make_uint4(hi0, hi1, lo0, lo1);
        }
    }

    const int lq = lane >> 2;         // 0..7  (groupID)
    const int lr = lane & 3;          // 0..3  (threadID-in-group)
    const int x0 = vc * SCALE + lq;   // pixel 0: x=lq; pixel 1: x=lq+8

    // ---- phase 2a: lw via split-tf32 MMA, exp, pack to bf16 A-fragments ----
    uint32_t ah[2][4][4], al[2][4][4];
    float inv[2][2];
    // per-mt A-lw fragments (tf32 hi/lo) and P constants
    uint32_t aw_h[2][4], aw_l[2][4];
    float P[2][2];
    {
        const float px0 = ((float)lq - 7.5f) * (1.0f / SCALE);
        const float px1 = ((float)(lq + 8) - 7.5f) * (1.0f / SCALE);
#pragma unroll
        for (int mt = 0; mt < 2; mt++) {
            const int tyc = zh * 8 + 2 * wid + mt;
            const int y = uc * SCALE + tyc;
            const float* gp0 = guide + (size_t)y * WH + x0;
            const float ga0 = gp0[0],  ga1 = gp0[HW],     ga2 = gp0[2 * HW];
            const float gb0 = gp0[8],  gb1 = gp0[HW + 8], gb2 = gp0[2 * HW + 8];
            const float py = ((float)tyc - 7.5f) * (1.0f / SCALE);
            const float pa0 = px0 * ct + py * st;
            const float pb0 = py * ct - px0 * st;
            const float pa1 = px1 * ct + py * st;
            const float pb1 = py * ct - px1 * st;

            P[mt][0] = -(pa0 * pa0 * isx + pb0 * pb0 * isy)
                       - (ga0 * ga0 + ga1 * ga1 + ga2 * ga2) * isr;
            P[mt][1] = -(pa1 * pa1 * isx + pb1 * pb1 * isy)
                       - (gb0 * gb0 + gb1 * gb1 + gb2 * gb2) * isr;

            // v[lr] and v[lr+4] for each pixel; v = (pa, pb, g0, g1, g2, 1, 0, 0)
            float v0p0 = (lr == 0) ? pa0 : (lr == 1) ? pb0 : (lr == 2) ? ga0 : ga1;
            float v0p1 = (lr == 0) ? pa1 : (lr == 1) ? pb1 : (lr == 2) ? gb0 : gb1;
            float v4p0 = (lr == 0) ? ga2 : (lr == 1) ? 1.0f : 0.0f;
            float v4p1 = (lr == 0) ? gb2 : (lr == 1) ? 1.0f : 0.0f;

            uint32_t h;
            h = f2tf32(v0p0); aw_h[mt][0] = h; aw_l[mt][0] = f2tf32(v0p0 - __uint_as_float(h));
            h = f2tf32(v0p1); aw_h[mt][1] = h; aw_l[mt][1] = f2tf32(v0p1 - __uint_as_float(h));
            h = f2tf32(v4p0); aw_h[mt][2] = h; aw_l[mt][2] = f2tf32(v4p0 - __uint_as_float(h));
            h = f2tf32(v4p1); aw_h[mt][3] = h; aw_l[mt][3] = f2tf32(v4p1 - __uint_as_float(h));
        }
    }

    float den[2][2] = {{0.f, 0.f}, {0.f, 0.f}};
#pragma unroll
    for (int ks = 0; ks < 4; ks++) {
        if (ks >= ksteps) {
#pragma unroll
            for (int mt = 0; mt < 2; mt++)
#pragma unroll
                for (int j = 0; j < 4; j++) { ah[mt][ks][j] = 0u; al[mt][ks][j] = 0u; }
            continue;
        }
#pragma unroll
        for (int j = 0; j < 2; j++) {
            const int nt = 2 * ks + j;      // covers kpair lr (cols 2lr,2lr+1)... j=0 -> kp lr; j=1 -> kp lr+4
            const int qoff = nt * 8 + lq;
            uint32_t b0h = Qh[lr * QSTR + qoff];
            uint32_t b1h = Qh[(lr + 4) * QSTR + qoff];
            uint32_t b0l = Ql[lr * QSTR + qoff];
            uint32_t b1l = Ql[(lr + 4) * QSTR + qoff];
#pragma unroll
            for (int mt = 0; mt < 2; mt++) {
                float d[4] = {P[mt][0], P[mt][0], P[mt][1], P[mt][1]};
                MMA_TF32K8(d, aw_h[mt][0], aw_h[mt][1], aw_h[mt][2], aw_h[mt][3], b0h, b1h);
                MMA_TF32K8(d, aw_l[mt][0], aw_l[mt][1], aw_l[mt][2], aw_l[mt][3], b0h, b1h);
                MMA_TF32K8(d, aw_h[mt][0], aw_h[mt][1], aw_h[mt][2], aw_h[mt][3], b0l, b1l);
                float e0 = __expf(d[0]);
                float e1 = __expf(d[1]);
                float e2 = __expf(d[2]);
                float e3 = __expf(d[3]);
                den[mt][0] += e0 + e1;
                den[mt][1] += e2 + e3;
                uint32_t hA = pack_bf16x2(e0, e1);
                uint32_t hB = pack_bf16x2(e2, e3);
                uint32_t lA = pack_bf16x2(e0 - __uint_as_float(hA << 16),
                                          e1 - __uint_as_float(hA & 0xffff0000u));
                uint32_t lB = pack_bf16x2(e2 - __uint_as_float(hB << 16),
                                          e3 - __uint_as_float(hB & 0xffff0000u));
                ah[mt][ks][2 * j]     = hA;   // pixel0 fragment (rows lq)
                ah[mt][ks][2 * j + 1] = hB;   // pixel1 fragment (rows lq+8)
                al[mt][ks][2 * j]     = lA;
                al[mt][ks][2 * j + 1] = lB;
            }
        }
    }
    // NOTE: fragment order fix — main MMA expects {p0 kpA, p1 kpA, p0 kpB, p1 kpB}
    // j=0 wrote slots 0,1 (kpair lr) and j=1 wrote slots 2,3 (kpair lr+4). Correct.

#pragma unroll
    for (int mt = 0; mt < 2; mt++) {
        float d0 = den[mt][0], d1 = den[mt][1];
        d0 += __shfl_xor_sync(0xffffffffu, d0, 1);
        d0 += __shfl_xor_sync(0xffffffffu, d0, 2);
        d1 += __shfl_xor_sync(0xffffffffu, d1, 1);
        d1 += __shfl_xor_sync(0xffffffffu, d1, 2);
        inv[mt][0] = 1.0f / fmaxf(d0, 1e-8f);
        inv[mt][1] = 1.0f / fmaxf(d1, 1e-8f);
    }

    __syncthreads();   // F4 ready

    // ---- phase 2b: stream channels; 1 LDS.128 feeds 6 MMAs ----
    const int ybase = uc * SCALE + zh * 8 + 2 * wid;
    float* ob0 = out + (size_t)ybase * WH + x0;          // mt 0
    float* ob1 = out + (size_t)(ybase + 1) * WH + x0;    // mt 1

#pragma unroll
    for (int ng = 0; ng < 8; ng++) {
#pragma unroll
        for (int h = 0; h < 2; h++) {
            const int cb = (2 * ng + h) * 8 + lq;
            float acc0[4] = {0.f, 0.f, 0.f, 0.f};
            float acc1[4] = {0.f, 0.f, 0.f, 0.f};
#pragma unroll
            for (int ks = 0; ks < 4; ks++) {
                if (ks >= ksteps) break;
                uint4 B = F4[(ks * 4 + lr) * CSTR4 + cb];
                MMA_BF16(acc0, ah[0][ks][0], ah[0][ks][1], ah[0][ks][2], ah[0][ks][3], B.x, B.y);
                MMA_BF16(acc0, al[0][ks][0], al[0][ks][1], al[0][ks][2], al[0][ks][3], B.x, B.y);
                MMA_BF16(acc0, ah[0][ks][0], ah[0][ks][1], ah[0][ks][2], ah[0][ks][3], B.z, B.w);
                MMA_BF16(acc1, ah[1][ks][0], ah[1][ks][1], ah[1][ks][2], ah[1][ks][3], B.x, B.y);
                MMA_BF16(acc1, al[1][ks][0], al[1][ks][1], al[1][ks][2], al[1][ks][3], B.x, B.y);
                MMA_BF16(acc1, ah[1][ks][0], ah[1][ks][1], ah[1][ks][2], ah[1][ks][3], B.z, B.w);
            }
            const int ch = (2 * ng + h) * 8 + lr * 2;
            float* o0 = ob0 + (size_t)ch * HW;
            float* o1 = ob1 + (size_t)ch * HW;
            o0[0]      = acc0[0] * inv[0][0];
            o0[HW]     = acc0[1] * inv[0][0];
            o0[8]      = acc0[2] * inv[0][1];
            o0[HW + 8] = acc0[3] * inv[0][1];
            o1[0]      = acc1[0] * inv[1][0];
            o1[HW]     = acc1[1] * inv[1][0];
            o1[8]      = acc1[2] * inv[1][1];
            o1[HW + 8] = acc1[3] * inv[1][1];
        }
    }
}

extern "C" void kernel_launch(void* const* d_in, const int* in_sizes, int n_in,
                              void* d_out, int out_size) {
    const float* feat  = (const float*)d_in[0];
    const float* guide = (const float*)d_in[1];
    const float* sx    = (const float*)d_in[2];
    const float* sy    = (const float*)d_in[3];
    const float* th    = (const float*)d_in[4];
    const float* sr    = (const float*)d_in[5];
    float* out = (float*)d_out;

    cudaFuncSetAttribute(jbu_main_kernel,
                         cudaFuncAttributeMaxDynamicSharedMemorySize, SMEM_BYTES);

    jbu_prep_kernel<<<512, 256>>>(feat, guide);
    dim3 grid(WL, HL, 2);
    jbu_main_kernel<<<grid, 128, SMEM_BYTES>>>(guide, sx, sy, th, sr, out);
}

// round 16
// speedup vs baseline: 1.5156x; 1.0231x over previous
#include <cuda_runtime.h>
#include <math.h>
#include <stdint.h>

#define SCALE 16
#define R_MAX 4
#define HL 32
#define WL 32
#define HH 512
#define WH 512
#define C_FEAT 128
#define HW (HH * WH)

// prep scratch
__device__ float g_guide_lr[3 * HL * WL];
__device__ float g_feat_t[HL * WL * C_FEAT];   // [spatial][channel]

// ---------------- dynamic smem layout (bytes) ----------------
#define CSTR4 130
#define QSTR  72
#define OFF_SCAL   0            // floats: ct, st, isx, isy, isr, Rsq
#define OFF_NACT   32
#define OFF_SI     64           // int[64]
#define OFF_DXF    320          // float[64]
#define OFF_DYF    576          // float[64]
#define OFF_F4     2432         // uint4[16][CSTR4]
#define OFF_QH     (OFF_F4 + 16 * CSTR4 * 16)      // 35712
#define OFF_QL     (OFF_QH + 8 * QSTR * 4)         // +2304
#define SMEM_BYTES (OFF_QL + 8 * QSTR * 4)         // 40320 B

static __device__ __forceinline__ uint32_t pack_bf16x2(float w0, float w1) {
    uint32_t r;
    asm("cvt.rn.bf16x2.f32 %0, %1, %2;" : "=r"(r) : "f"(w1), "f"(w0));
    return r;
}

static __device__ __forceinline__ uint32_t f2tf32(float f) {
    uint32_t r;
    asm("cvt.rna.tf32.f32 %0, %1;" : "=r"(r) : "f"(f));
    return r;
}

#define MMA_BF16(d, a0, a1, a2, a3, b0, b1) \
    asm volatile("mma.sync.aligned.m16n8k16.row.col.f32.bf16.bf16.f32 " \
        "{%0,%1,%2,%3}, {%4,%5,%6,%7}, {%8,%9}, {%0,%1,%2,%3};" \
        : "+f"((d)[0]), "+f"((d)[1]), "+f"((d)[2]), "+f"((d)[3]) \
        : "r"(a0), "r"(a1), "r"(a2), "r"(a3), "r"(b0), "r"(b1))

#define MMA_TF32K8(d, a0, a1, a2, a3, b0, b1) \
    asm volatile("mma.sync.aligned.m16n8k8.row.col.f32.tf32.tf32.f32 " \
        "{%0,%1,%2,%3}, {%4,%5,%6,%7}, {%8,%9}, {%0,%1,%2,%3};" \
        : "+f"((d)[0]), "+f"((d)[1]), "+f"((d)[2]), "+f"((d)[3]) \
        : "r"(a0), "r"(a1), "r"(a2), "r"(a3), "r"(b0), "r"(b1))

// ---------------------------------------------------------------------------
// Prep: transpose feat to channel-minor; bilinear-downsample guide (separable,
// rows then columns, matching the reference).
// ---------------------------------------------------------------------------
__global__ void jbu_prep_kernel(const float* __restrict__ feat,
                                const float* __restrict__ guide) {
    int idx = blockIdx.x * blockDim.x + threadIdx.x;

    if (idx < HL * WL * C_FEAT) {
        int c = idx & (C_FEAT - 1);
        int s = idx >> 7;
        g_feat_t[idx] = feat[c * (HL * WL) + s];
    }
    if (idx < 3 * HL * WL) {
        int c = idx >> 10;
        int rem = idx & 1023;
        int i = rem >> 5;
        int j = rem & 31;

        float srcy = fmaxf((i + 0.5f) * ((float)HH / HL) - 0.5f, 0.0f);
        int r0 = (int)floorf(srcy);
        float tr = srcy - (float)r0;
        int r0c = min(max(r0, 0), HH - 1);
        int r1c = min(max(r0 + 1, 0), HH - 1);

        float srcx = fmaxf((j + 0.5f) * ((float)WH / WL) - 0.5f, 0.0f);
        int c0 = (int)floorf(srcx);
        float tc = srcx - (float)c0;
        int c0c = min(max(c0, 0), WH - 1);
        int c1c = min(max(c0 + 1, 0), WH - 1);

        const float* g = guide + c * HW;
        float v0 = g[r0c * WH + c0c] * (1.0f - tr) + g[r1c * WH + c0c] * tr;
        float v1 = g[r0c * WH + c1c] * (1.0f - tr) + g[r1c * WH + c1c] * tr;
        g_guide_lr[idx] = v0 * (1.0f - tc) + v1 * tc;
    }
}

// ---------------------------------------------------------------------------
// Main: one block per HALF LR cell (8 HR rows x 16 cols x 128 ch).
// Pixel mapping: MMA row r -> x = 2*(r&7) + (r>>3), so each thread's C
// fragment holds two CONSECUTIVE x -> float2 stores (half the STG wavefronts).
// lw via split-tf32 m16n8k8 MMA (C seeded with P); main GEMM bf16 hh+lh+hl.
// ---------------------------------------------------------------------------
__global__ __launch_bounds__(128, 5)
void jbu_main_kernel(const float* __restrict__ guide,
                     const float* __restrict__ sx_raw,
                     const float* __restrict__ sy_raw,
                     const float* __restrict__ th_raw,
                     const float* __restrict__ sr_raw,
                     float* __restrict__ out) {
    extern __shared__ __align__(16) char smem[];

    float*    s_scal = (float*)(smem + OFF_SCAL);
    int*      s_nactp = (int*)(smem + OFF_NACT);
    int*      s_si   = (int*)(smem + OFF_SI);
    float*    s_dxf  = (float*)(smem + OFF_DXF);
    float*    s_dyf  = (float*)(smem + OFF_DYF);
    uint4*    F4     = (uint4*)(smem + OFF_F4);
    uint32_t* Qh     = (uint32_t*)(smem + OFF_QH);
    uint32_t* Ql     = (uint32_t*)(smem + OFF_QL);

    const int uc = blockIdx.y;
    const int vc = blockIdx.x;
    const int zh = blockIdx.z;       // 0/1: which 8-row half of the 16x16 tile
    const int tid = threadIdx.x;
    const int wid = tid >> 5;        // 0..3
    const int lane = tid & 31;

    // ---- phase 0: params + offset compaction (warp 0, ballot-based) ----
    if (wid == 0) {
        if (lane == 0) {
            int cell = uc * WL + vc;
            float sx = fmaxf(expf(sx_raw[cell]), 1e-6f);
            float sy = fmaxf(expf(sy_raw[cell]), 1e-6f);
            float th = 3.14159265358979323846f * tanhf(th_raw[cell]);
            float sr = fmaxf(expf(sr_raw[cell]), 1e-6f);
            float rr = fminf(fmaxf(2.0f * fmaxf(sx, sy), 1.0f), (float)R_MAX);
            s_scal[0] = cosf(th);
            s_scal[1] = sinf(th);
            s_scal[2] = 1.0f / (2.0f * sx * sx + 1e-8f);
            s_scal[3] = 1.0f / (2.0f * sy * sy + 1e-8f);
            s_scal[4] = 1.0f / (2.0f * sr * sr + 1e-8f);
            s_scal[5] = rr * rr;
        }
        __syncwarp();
        const float Rsq = s_scal[5];
        int base = 0;
#pragma unroll
        for (int chnk = 0; chnk < 3; chnk++) {
            int i = chnk * 32 + lane;
            int dy = i / 9 - R_MAX;
            int dx = i - (i / 9) * 9 - R_MAX;
            bool act = (i < 81) && ((float)(dy * dy + dx * dx) <= Rsq);
            unsigned m = __ballot_sync(0xffffffffu, act);
            int pos = base + __popc(m & ((1u << lane) - 1u));
            if (act) {
                int ui = min(max(uc + dy, 0), HL - 1);
                int vi = min(max(vc + dx, 0), WL - 1);
                s_dyf[pos] = (float)(uc - ui);
                s_dxf[pos] = (float)(vc - vi);
                s_si[pos]  = ui * WL + vi;
            }
            base += __popc(m);
        }
        if (lane == 0) *s_nactp = base;
    }
    __syncthreads();

    const int nact = *s_nactp;                 // <= 49
    const int ksteps = (nact + 15) >> 4;       // <= 4
    const float ct  = s_scal[0];
    const float st  = s_scal[1];
    const float isx = s_scal[2];
    const float isy = s_scal[3];
    const float isr = s_scal[4];

    // ---- build Q (lw coefficient matrix): threads 0..63, one offset each ----
    if (tid < 64) {
        float q[6];
        if (tid < nact) {
            int si = s_si[tid];
            float fdx = s_dxf[tid];
            float fdy = s_dyf[tid];
            float gl0 = g_guide_lr[si];
            float gl1 = g_guide_lr[HL * WL + si];
            float gl2 = g_guide_lr[2 * HL * WL + si];
            float A = fdx * ct + fdy * st;
            float B = fdy * ct - fdx * st;
            float D = (gl0 * gl0 + gl1 * gl1 + gl2 * gl2) * isr;
            q[0] = -2.0f * A * isx;
            q[1] = -2.0f * B * isy;
            q[2] = 2.0f * gl0 * isr;
            q[3] = 2.0f * gl1 * isr;
            q[4] = 2.0f * gl2 * isr;
            q[5] = -(A * A * isx + B * B * isy + D);
        } else {
            q[0] = q[1] = q[2] = q[3] = q[4] = 0.0f;
            q[5] = -1e30f;   // lw -> -1e30 -> w = 0
        }
#pragma unroll
        for (int r = 0; r < 6; r++) {
            uint32_t h = f2tf32(q[r]);
            Qh[r * QSTR + tid] = h;
            Ql[r * QSTR + tid] = f2tf32(q[r] - __uint_as_float(h));
        }
        Qh[6 * QSTR + tid] = 0u; Qh[7 * QSTR + tid] = 0u;
        Ql[6 * QSTR + tid] = 0u; Ql[7 * QSTR + tid] = 0u;
    }
    __syncthreads();

    // ---- phase 1: build F4 (all 128 threads; consecutive c -> conflict-free) ----
    {
        const int nent = ksteps * 4 * C_FEAT;
        for (int e = tid; e < nent; e += 128) {
            int c = e & 127;
            int q = e >> 7;                // ks*4 + lr_b
            int kp0 = (q >> 2) * 8 + (q & 3);
            int kp1 = kp0 + 4;
            int k00 = 2 * kp0, k01 = k00 + 1;
            int k10 = 2 * kp1, k11 = k10 + 1;
            float f00 = (k00 < nact) ? g_feat_t[s_si[k00] * C_FEAT + c] : 0.0f;
            float f01 = (k01 < nact) ? g_feat_t[s_si[k01] * C_FEAT + c] : 0.0f;
            float f10 = (k10 < nact) ? g_feat_t[s_si[k10] * C_FEAT + c] : 0.0f;
            float f11 = (k11 < nact) ? g_feat_t[s_si[k11] * C_FEAT + c] : 0.0f;
            uint32_t hi0 = pack_bf16x2(f00, f01);
            uint32_t hi1 = pack_bf16x2(f10, f11);
            uint32_t lo0 = pack_bf16x2(f00 - __uint_as_float(hi0 << 16),
                                       f01 - __uint_as_float(hi0 & 0xffff0000u));
            uint32_t lo1 = pack_bf16x2(f10 - __uint_as_float(hi1 << 16),
                                       f11 - __uint_as_float(hi1 & 0xffff0000u));
            F4[q * CSTR4 + c] = make_uint4(hi0, hi1, lo0, lo1);
        }
    }

    const int lq = lane >> 2;         // 0..7  (groupID)
    const int lr = lane & 3;          // 0..3  (threadID-in-group)
    // NEW pixel mapping: row lq -> x = 2*lq, row lq+8 -> x = 2*lq+1
    const int x0 = vc * SCALE + 2 * lq;

    // ---- phase 2a: lw via split-tf32 MMA, exp, pack to bf16 A-fragments ----
    uint32_t ah[2][4][4], al[2][4][4];
    float inv[2][2];
    uint32_t aw_h[2][4], aw_l[2][4];
    float P[2][2];
    {
        const float px0 = ((float)(2 * lq) - 7.5f) * (1.0f / SCALE);
        const float px1 = ((float)(2 * lq + 1) - 7.5f) * (1.0f / SCALE);
#pragma unroll
        for (int mt = 0; mt < 2; mt++) {
            const int tyc = zh * 8 + 2 * wid + mt;
            const int y = uc * SCALE + tyc;
            const float* gp0 = guide + (size_t)y * WH + x0;
            // pixel 0 = x0, pixel 1 = x0+1 (adjacent -> float2 loads)
            float2 g01_0 = *(const float2*)(gp0);
            float2 g01_1 = *(const float2*)(gp0 + HW);
            float2 g01_2 = *(const float2*)(gp0 + 2 * HW);
            const float ga0 = g01_0.x, ga1 = g01_1.x, ga2 = g01_2.x;
            const float gb0 = g01_0.y, gb1 = g01_1.y, gb2 = g01_2.y;
            const float py = ((float)tyc - 7.5f) * (1.0f / SCALE);
            const float pa0 = px0 * ct + py * st;
            const float pb0 = py * ct - px0 * st;
            const float pa1 = px1 * ct + py * st;
            const float pb1 = py * ct - px1 * st;

            P[mt][0] = -(pa0 * pa0 * isx + pb0 * pb0 * isy)
                       - (ga0 * ga0 + ga1 * ga1 + ga2 * ga2) * isr;
            P[mt][1] = -(pa1 * pa1 * isx + pb1 * pb1 * isy)
                       - (gb0 * gb0 + gb1 * gb1 + gb2 * gb2) * isr;

            // v[lr] and v[lr+4] for each pixel; v = (pa, pb, g0, g1, g2, 1, 0, 0)
            float v0p0 = (lr == 0) ? pa0 : (lr == 1) ? pb0 : (lr == 2) ? ga0 : ga1;
            float v0p1 = (lr == 0) ? pa1 : (lr == 1) ? pb1 : (lr == 2) ? gb0 : gb1;
            float v4p0 = (lr == 0) ? ga2 : (lr == 1) ? 1.0f : 0.0f;
            float v4p1 = (lr == 0) ? gb2 : (lr == 1) ? 1.0f : 0.0f;

            uint32_t h;
            h = f2tf32(v0p0); aw_h[mt][0] = h; aw_l[mt][0] = f2tf32(v0p0 - __uint_as_float(h));
            h = f2tf32(v0p1); aw_h[mt][1] = h; aw_l[mt][1] = f2tf32(v0p1 - __uint_as_float(h));
            h = f2tf32(v4p0); aw_h[mt][2] = h; aw_l[mt][2] = f2tf32(v4p0 - __uint_as_float(h));
            h = f2tf32(v4p1); aw_h[mt][3] = h; aw_l[mt][3] = f2tf32(v4p1 - __uint_as_float(h));
        }
    }

    float den[2][2] = {{0.f, 0.f}, {0.f, 0.f}};
#pragma unroll
    for (int ks = 0; ks < 4; ks++) {
        if (ks >= ksteps) {
#pragma unroll
            for (int mt = 0; mt < 2; mt++)
#pragma unroll
                for (int j = 0; j < 4; j++) { ah[mt][ks][j] = 0u; al[mt][ks][j] = 0u; }
            continue;
        }
#pragma unroll
        for (int j = 0; j < 2; j++) {
            const int nt = 2 * ks + j;      // j=0 -> kpair lr; j=1 -> kpair lr+4
            const int qoff = nt * 8 + lq;
            uint32_t b0h = Qh[lr * QSTR + qoff];
            uint32_t b1h = Qh[(lr + 4) * QSTR + qoff];
            uint32_t b0l = Ql[lr * QSTR + qoff];
            uint32_t b1l = Ql[(lr + 4) * QSTR + qoff];
#pragma unroll
            for (int mt = 0; mt < 2; mt++) {
                float d[4] = {P[mt][0], P[mt][0], P[mt][1], P[mt][1]};
                MMA_TF32K8(d, aw_h[mt][0], aw_h[mt][1], aw_h[mt][2], aw_h[mt][3], b0h, b1h);
                MMA_TF32K8(d, aw_l[mt][0], aw_l[mt][1], aw_l[mt][2], aw_l[mt][3], b0h, b1h);
                MMA_TF32K8(d, aw_h[mt][0], aw_h[mt][1], aw_h[mt][2], aw_h[mt][3], b0l, b1l);
                float e0 = __expf(d[0]);
                float e1 = __expf(d[1]);
                float e2 = __expf(d[2]);
                float e3 = __expf(d[3]);
                den[mt][0] += e0 + e1;
                den[mt][1] += e2 + e3;
                uint32_t hA = pack_bf16x2(e0, e1);
                uint32_t hB = pack_bf16x2(e2, e3);
                uint32_t lA = pack_bf16x2(e0 - __uint_as_float(hA << 16),
                                          e1 - __uint_as_float(hA & 0xffff0000u));
                uint32_t lB = pack_bf16x2(e2 - __uint_as_float(hB << 16),
                                          e3 - __uint_as_float(hB & 0xffff0000u));
                ah[mt][ks][2 * j]     = hA;   // pixel0 fragment (row lq)
                ah[mt][ks][2 * j + 1] = hB;   // pixel1 fragment (row lq+8)
                al[mt][ks][2 * j]     = lA;
                al[mt][ks][2 * j + 1] = lB;
            }
        }
    }

#pragma unroll
    for (int mt = 0; mt < 2; mt++) {
        float d0 = den[mt][0], d1 = den[mt][1];
        d0 += __shfl_xor_sync(0xffffffffu, d0, 1);
        d0 += __shfl_xor_sync(0xffffffffu, d0, 2);
        d1 += __shfl_xor_sync(0xffffffffu, d1, 1);
        d1 += __shfl_xor_sync(0xffffffffu, d1, 2);
        inv[mt][0] = 1.0f / fmaxf(d0, 1e-8f);
        inv[mt][1] = 1.0f / fmaxf(d1, 1e-8f);
    }

    __syncthreads();   // F4 ready

    // ---- phase 2b: stream channels; float2 stores (consecutive x) ----
    const int ybase = uc * SCALE + zh * 8 + 2 * wid;
    float* ob0 = out + (size_t)ybase * WH + x0;          // mt 0
    float* ob1 = out + (size_t)(ybase + 1) * WH + x0;    // mt 1

#pragma unroll
    for (int ng = 0; ng < 8; ng++) {
#pragma unroll
        for (int h = 0; h < 2; h++) {
            const int cb = (2 * ng + h) * 8 + lq;
            float acc0[4] = {0.f, 0.f, 0.f, 0.f};
            float acc1[4] = {0.f, 0.f, 0.f, 0.f};
#pragma unroll
            for (int ks = 0; ks < 4; ks++) {
                if (ks >= ksteps) break;
                uint4 B = F4[(ks * 4 + lr) * CSTR4 + cb];
                MMA_BF16(acc0, ah[0][ks][0], ah[0][ks][1], ah[0][ks][2], ah[0][ks][3], B.x, B.y);
                MMA_BF16(acc0, al[0][ks][0], al[0][ks][1], al[0][ks][2], al[0][ks][3], B.x, B.y);
                MMA_BF16(acc0, ah[0][ks][0], ah[0][ks][1], ah[0][ks][2], ah[0][ks][3], B.z, B.w);
                MMA_BF16(acc1, ah[1][ks][0], ah[1][ks][1], ah[1][ks][2], ah[1][ks][3], B.x, B.y);
                MMA_BF16(acc1, al[1][ks][0], al[1][ks][1], al[1][ks][2], al[1][ks][3], B.x, B.y);
                MMA_BF16(acc1, ah[1][ks][0], ah[1][ks][1], ah[1][ks][2], ah[1][ks][3], B.z, B.w);
            }
            // acc[0] = (ch c0, x0), acc[2] = (c0, x0+1); acc[1]/acc[3] same for c1
            const int ch = (2 * ng + h) * 8 + lr * 2;
            float* o0 = ob0 + (size_t)ch * HW;
            float* o1 = ob1 + (size_t)ch * HW;
            *(float2*)(o0)      = make_float2(acc0[0] * inv[0][0], acc0[2] * inv[0][1]);
            *(float2*)(o0 + HW) = make_float2(acc0[1] * inv[0][0], acc0[3] * inv[0][1]);
            *(float2*)(o1)      = make_float2(acc1[0] * inv[1][0], acc1[2] * inv[1][1]);
            *(float2*)(o1 + HW) = make_float2(acc1[1] * inv[1][0], acc1[3] * inv[1][1]);
        }
    }
}

extern "C" void kernel_launch(void* const* d_in, const int* in_sizes, int n_in,
                              void* d_out, int out_size) {
    const float* feat  = (const float*)d_in[0];
    const float* guide = (const float*)d_in[1];
    const float* sx    = (const float*)d_in[2];
    const float* sy    = (const float*)d_in[3];
    const float* th    = (const float*)d_in[4];
    const float* sr    = (const float*)d_in[5];
    float* out = (float*)d_out;

    cudaFuncSetAttribute(jbu_main_kernel,
                         cudaFuncAttributeMaxDynamicSharedMemorySize, SMEM_BYTES);

    jbu_prep_kernel<<<512, 256>>>(feat, guide);
    dim3 grid(WL, HL, 2);
    jbu_main_kernel<<<grid, 128, SMEM_BYTES>>>(guide, sx, sy, th, sr, out);
}